// round 12
// baseline (speedup 1.0000x reference)
#include <cuda_runtime.h>
#include <cstdint>

#define D_DIM 128
#define MAX_N 200064
#define MAX_K 512

__device__ float g_sums[MAX_K * D_DIM];
__device__ int   g_counts[MAX_K];
__device__ int   g_assign[MAX_N];
__device__ float g_c2[MAX_K];
__device__ float g_f2[MAX_N];
__device__ uint32_t g_Chi[MAX_K * D_DIM];   // tf32 hi split of centers (bit patterns)
__device__ uint32_t g_Clo[MAX_K * D_DIM];   // tf32 lo split

__device__ __forceinline__ uint32_t f2tf32(float x) {
    uint32_t r; asm("cvt.rna.tf32.f32 %0, %1;" : "=r"(r) : "f"(x)); return r;
}
__device__ __forceinline__ void mma_tf32(float* d, const uint32_t* a, const uint32_t* b) {
    asm volatile(
        "mma.sync.aligned.m16n8k8.row.col.f32.tf32.tf32.f32 "
        "{%0,%1,%2,%3}, {%4,%5,%6,%7}, {%8,%9}, {%0,%1,%2,%3};"
        : "+f"(d[0]), "+f"(d[1]), "+f"(d[2]), "+f"(d[3])
        : "r"(a[0]), "r"(a[1]), "r"(a[2]), "r"(a[3]), "r"(b[0]), "r"(b[1]));
}

// ---------------------------------------------------------------------------
// Fused prep: zero sums/counts, tf32-split C, f2, c2.
// ---------------------------------------------------------------------------
__global__ void prep_kernel(const float* __restrict__ F,
                            const float* __restrict__ C, int N, int K) {
    const int t = blockIdx.x * blockDim.x + threadIdx.x;
    const int KD = K * D_DIM;
    if (t < KD) {
        g_sums[t] = 0.0f;
        float v = C[t];
        uint32_t hb = f2tf32(v);
        float hf = __uint_as_float(hb);
        uint32_t lb = f2tf32(v - hf);
        g_Chi[t] = hb; g_Clo[t] = lb;
    }
    if (t < K) g_counts[t] = 0;

    const int w = t >> 5;
    const int lane = t & 31;
    if (w < N) {
        float4 v = reinterpret_cast<const float4*>(F + (size_t)w * D_DIM)[lane];
        float s = v.x * v.x + v.y * v.y + v.z * v.z + v.w * v.w;
        #pragma unroll
        for (int o = 16; o > 0; o >>= 1) s += __shfl_xor_sync(0xffffffffu, s, o);
        if (lane == 0) g_f2[w] = s;
    } else if (w < N + K) {
        int k = w - N;
        float4 v = reinterpret_cast<const float4*>(C + (size_t)k * D_DIM)[lane];
        float s = v.x * v.x + v.y * v.y + v.z * v.z + v.w * v.w;
        #pragma unroll
        for (int o = 16; o > 0; o >>= 1) s += __shfl_xor_sync(0xffffffffu, s, o);
        if (lane == 0) g_c2[k] = s;
    }
}

// ---------------------------------------------------------------------------
// Assignment via mma.sync tf32x2 (3-pass emulated fp32):
//   block = 256 thr / 8 warps (4 M-warps x 2 N-warps)
//   block tile 128 points x 128 centers, warp tile 32 x 64, d-chunk 16
//   smem: hi/lo tf32 tiles, [d][row] pitch 136 (conflict-free)
// ---------------------------------------------------------------------------
#define SP 136

__global__ __launch_bounds__(256, 2) void assign_kernel(
    const float* __restrict__ F, int N, int K)
{
    __shared__ uint32_t sFh[16 * SP], sFl[16 * SP];
    __shared__ uint32_t sCh[16 * SP], sCl[16 * SP];
    __shared__ float sBv[2][128];
    __shared__ int   sBi[2][128];

    const int tid  = threadIdx.x;
    const int wid  = tid >> 5;
    const int lane = tid & 31;
    const int mw = wid & 3;          // M warp 0..3
    const int nw = wid >> 2;         // N warp 0..1
    const int g  = lane >> 2;        // group row / B col 0..7
    const int q  = lane & 3;         // quad (k index) 0..3
    const int p0 = blockIdx.x * 128;

    float D[2][8][4];
    #pragma unroll
    for (int mt = 0; mt < 2; mt++)
        #pragma unroll
        for (int n = 0; n < 8; n++)
            #pragma unroll
            for (int e = 0; e < 4; e++) D[mt][n][e] = 0.0f;

    float bestv[4];
    int   besti[4];
    float f2v[4];
    #pragma unroll
    for (int s = 0; s < 4; s++) {
        bestv[s] = __int_as_float(0x7f800000); besti[s] = 0;
        int row = p0 + mw * 32 + (s >> 1) * 16 + g + 8 * (s & 1);
        if (row >= N) row = N - 1;
        f2v[s] = g_f2[row];
    }

    const int nkt = K >> 7;          // k-tiles of 128 centers
    for (int kt = 0; kt < nkt; ++kt) {
        for (int dc = 0; dc < 8; ++dc) {
            const int d0 = dc * 16;
            __syncthreads();
            // ---- loaders: t<128 -> F row t (split on the fly); t>=128 -> C row ----
            if (tid < 128) {
                int prow = p0 + tid; if (prow >= N) prow = N - 1;
                const float4* src = reinterpret_cast<const float4*>(
                    F + (size_t)prow * D_DIM + d0);
                #pragma unroll
                for (int qq = 0; qq < 4; ++qq) {
                    float4 v = src[qq];
                    float vv[4] = { v.x, v.y, v.z, v.w };
                    #pragma unroll
                    for (int e = 0; e < 4; ++e) {
                        int d = qq * 4 + e;
                        uint32_t hb = f2tf32(vv[e]);
                        float hf = __uint_as_float(hb);
                        uint32_t lb = f2tf32(vv[e] - hf);
                        sFh[d * SP + tid] = hb;
                        sFl[d * SP + tid] = lb;
                    }
                }
            } else {
                int crow = tid - 128;
                size_t base = (size_t)(kt * 128 + crow) * D_DIM + d0;
                const uint4* srcH = reinterpret_cast<const uint4*>(g_Chi + base);
                const uint4* srcL = reinterpret_cast<const uint4*>(g_Clo + base);
                #pragma unroll
                for (int qq = 0; qq < 4; ++qq) {
                    uint4 h = srcH[qq];
                    uint4 l = srcL[qq];
                    int d = qq * 4;
                    sCh[(d+0) * SP + crow] = h.x; sCh[(d+1) * SP + crow] = h.y;
                    sCh[(d+2) * SP + crow] = h.z; sCh[(d+3) * SP + crow] = h.w;
                    sCl[(d+0) * SP + crow] = l.x; sCl[(d+1) * SP + crow] = l.y;
                    sCl[(d+2) * SP + crow] = l.z; sCl[(d+3) * SP + crow] = l.w;
                }
            }
            __syncthreads();

            // ---- compute: 2 k-steps of 8 ----
            #pragma unroll
            for (int ks = 0; ks < 2; ++ks) {
                const int kk = ks * 8;
                uint32_t ah[2][4], al[2][4];
                #pragma unroll
                for (int mt = 0; mt < 2; ++mt) {
                    const int rb = mw * 32 + mt * 16 + g;
                    ah[mt][0] = sFh[(kk + q) * SP + rb];
                    ah[mt][1] = sFh[(kk + q) * SP + rb + 8];
                    ah[mt][2] = sFh[(kk + q + 4) * SP + rb];
                    ah[mt][3] = sFh[(kk + q + 4) * SP + rb + 8];
                    al[mt][0] = sFl[(kk + q) * SP + rb];
                    al[mt][1] = sFl[(kk + q) * SP + rb + 8];
                    al[mt][2] = sFl[(kk + q + 4) * SP + rb];
                    al[mt][3] = sFl[(kk + q + 4) * SP + rb + 8];
                }
                #pragma unroll
                for (int n = 0; n < 8; ++n) {
                    const int cb = nw * 64 + n * 8 + g;
                    uint32_t bh[2], bl[2];
                    bh[0] = sCh[(kk + q) * SP + cb];
                    bh[1] = sCh[(kk + q + 4) * SP + cb];
                    bl[0] = sCl[(kk + q) * SP + cb];
                    bl[1] = sCl[(kk + q + 4) * SP + cb];
                    #pragma unroll
                    for (int mt = 0; mt < 2; ++mt) {
                        mma_tf32(D[mt][n], ah[mt], bh);   // hh
                        mma_tf32(D[mt][n], al[mt], bh);   // lh
                        mma_tf32(D[mt][n], ah[mt], bl);   // hl
                    }
                }
            }
        }

        // ---- score this k-tile, reset D ----
        #pragma unroll
        for (int n = 0; n < 8; ++n) {
            const int cb = kt * 128 + nw * 64 + n * 8 + 2 * q;
            const float c2a = g_c2[cb];
            const float c2b = g_c2[cb + 1];
            #pragma unroll
            for (int mt = 0; mt < 2; ++mt) {
                #pragma unroll
                for (int h = 0; h < 2; ++h) {
                    const int s = mt * 2 + h;
                    float d0v = D[mt][n][h * 2 + 0];
                    float d1v = D[mt][n][h * 2 + 1];
                    float sa = (f2v[s] - 2.0f * d0v) + c2a;
                    float sb = (f2v[s] - 2.0f * d1v) + c2b;
                    if (sa < bestv[s]) { bestv[s] = sa; besti[s] = cb; }
                    if (sb < bestv[s]) { bestv[s] = sb; besti[s] = cb + 1; }
                    D[mt][n][h * 2 + 0] = 0.0f;
                    D[mt][n][h * 2 + 1] = 0.0f;
                }
            }
        }
    }

    // ---- reduce across the 4 quad lanes (same rows) ----
    #pragma unroll
    for (int s = 0; s < 4; ++s) {
        float v  = bestv[s];
        int   ix = besti[s];
        #pragma unroll
        for (int off = 1; off < 4; off <<= 1) {
            float ov = __shfl_down_sync(0xffffffffu, v, off, 4);
            int   oi = __shfl_down_sync(0xffffffffu, ix, off, 4);
            if (ov < v || (ov == v && oi < ix)) { v = ov; ix = oi; }
        }
        if (q == 0) {
            int row = mw * 32 + (s >> 1) * 16 + g + 8 * (s & 1);
            sBv[nw][row] = v;
            sBi[nw][row] = ix;
        }
    }
    __syncthreads();

    if (tid < 128) {
        float v0 = sBv[0][tid]; int i0 = sBi[0][tid];
        float v1 = sBv[1][tid]; int i1 = sBi[1][tid];
        int best = (v1 < v0 || (v1 == v0 && i1 < i0)) ? i1 : i0;
        if (p0 + tid < N) g_assign[p0 + tid] = best;
    }
}

// ---------------------------------------------------------------------------
__global__ void seg_kernel(const float* __restrict__ F, int N) {
    int w = (blockIdx.x * blockDim.x + threadIdx.x) >> 5;
    int lane = threadIdx.x & 31;
    if (w >= N) return;
    int a = g_assign[w];
    float4 v = reinterpret_cast<const float4*>(F + (size_t)w * D_DIM)[lane];
    float* dst = g_sums + (size_t)a * D_DIM + lane * 4;
    asm volatile("red.global.add.v4.f32 [%0], {%1, %2, %3, %4};"
                 :: "l"(dst), "f"(v.x), "f"(v.y), "f"(v.z), "f"(v.w)
                 : "memory");
    if (lane == 0) atomicAdd(&g_counts[a], 1);
}

__global__ void final_kernel(float* __restrict__ out, int KD, int nAssign) {
    int i = blockIdx.x * blockDim.x + threadIdx.x;
    if (i < KD) {
        float c = (float)g_counts[i / D_DIM];
        out[i] = g_sums[i] / fmaxf(c, 1.0f);
    } else {
        int a = i - KD;
        if (a < nAssign) out[KD + a] = (float)g_assign[a];
    }
}

// ---------------------------------------------------------------------------
extern "C" void kernel_launch(void* const* d_in, const int* in_sizes, int n_in,
                              void* d_out, int out_size)
{
    (void)n_in;
    const float* F = (const float*)d_in[0];
    const float* C = (const float*)d_in[1];
    const int D = D_DIM;
    const int N = in_sizes[0] / D;
    const int K = in_sizes[1] / D;
    float* out = (float*)d_out;
    const int KD = K * D;

    const int prepThreads = (N + K) * 32;
    prep_kernel<<<(prepThreads + 255) / 256, 256>>>(F, C, N, K);
    assign_kernel<<<(N + 127) / 128, 256>>>(F, N, K);
    seg_kernel<<<(N + 7) / 8, 256>>>(F, N);

    int centersPart, assignPart;
    if (out_size >= KD + N)      { centersPart = KD; assignPart = N; }
    else if (out_size >= KD)     { centersPart = KD; assignPart = out_size - KD; }
    else                         { centersPart = 0;  assignPart = out_size; }
    int total = centersPart + assignPart;
    if (total > 0)
        final_kernel<<<(total + 255) / 256, 256>>>(out, centersPart, assignPart);
}

// round 13
// speedup vs baseline: 1.0142x; 1.0142x over previous
#include <cuda_runtime.h>
#include <cstdint>

#define D_DIM 128
#define MAX_N 200064
#define MAX_K 512

__device__ float g_sums[MAX_K * D_DIM];
__device__ int   g_counts[MAX_K];
__device__ int   g_assign[MAX_N];
__device__ float g_c2[MAX_K];
__device__ float g_f2[MAX_N];
__device__ uint32_t g_Chi[MAX_K * D_DIM];   // tf32 hi split of centers
__device__ uint32_t g_Clo[MAX_K * D_DIM];   // tf32 lo split

__device__ __forceinline__ uint32_t f2tf32(float x) {
    uint32_t r; asm("cvt.rna.tf32.f32 %0, %1;" : "=r"(r) : "f"(x)); return r;
}
__device__ __forceinline__ void mma_tf32(float* d, const uint32_t* a,
                                         uint32_t b0, uint32_t b1) {
    asm volatile(
        "mma.sync.aligned.m16n8k8.row.col.f32.tf32.tf32.f32 "
        "{%0,%1,%2,%3}, {%4,%5,%6,%7}, {%8,%9}, {%0,%1,%2,%3};"
        : "+f"(d[0]), "+f"(d[1]), "+f"(d[2]), "+f"(d[3])
        : "r"(a[0]), "r"(a[1]), "r"(a[2]), "r"(a[3]), "r"(b0), "r"(b1));
}

// ---------------------------------------------------------------------------
// Fused prep: zero sums/counts, tf32-split C, f2, c2.
// ---------------------------------------------------------------------------
__global__ void prep_kernel(const float* __restrict__ F,
                            const float* __restrict__ C, int N, int K) {
    const int t = blockIdx.x * blockDim.x + threadIdx.x;
    const int KD = K * D_DIM;
    if (t < KD) {
        g_sums[t] = 0.0f;
        float v = C[t];
        uint32_t hb = f2tf32(v);
        uint32_t lb = f2tf32(v - __uint_as_float(hb));
        g_Chi[t] = hb; g_Clo[t] = lb;
    }
    if (t < K) g_counts[t] = 0;

    const int w = t >> 5;
    const int lane = t & 31;
    if (w < N) {
        float4 v = reinterpret_cast<const float4*>(F + (size_t)w * D_DIM)[lane];
        float s = v.x * v.x + v.y * v.y + v.z * v.z + v.w * v.w;
        #pragma unroll
        for (int o = 16; o > 0; o >>= 1) s += __shfl_xor_sync(0xffffffffu, s, o);
        if (lane == 0) g_f2[w] = s;
    } else if (w < N + K) {
        int k = w - N;
        float4 v = reinterpret_cast<const float4*>(C + (size_t)k * D_DIM)[lane];
        float s = v.x * v.x + v.y * v.y + v.z * v.z + v.w * v.w;
        #pragma unroll
        for (int o = 16; o > 0; o >>= 1) s += __shfl_xor_sync(0xffffffffu, s, o);
        if (lane == 0) g_c2[k] = s;
    }
}

// ---------------------------------------------------------------------------
// tf32x2 3-pass mma assignment with FRAGMENT-STAGED smem:
//   sA (128KB): F tile split hi/lo, laid out so each A-fragment = 1 LDS.128.
//     float idx = (((mwmt*16 + ks)*2 + split)*32 + lane)*4 + r
//       mwmt = row>>4, r = ((d>>2)&1)*2 + ((row>>3)&1), lane = (row&7)*4 + (d&3)
//   sB (2 x 16KB, double-buffered): C chunk (128 centers x 16 d) staged so each
//     (n, split) fragment pair for BOTH k-steps = 1 LDS.128:
//     float idx = (((c>>3)*2 + split)*32 + (c&7)*4 + (dd&3))*4 + (dd>>3)*2 + ((dd>>2)&1)
// Block: 256 thr / 8 warps (4 M x 2 N), tile 128 pts x 128 centers.
// ---------------------------------------------------------------------------
#define SA_BYTES  131072
#define SB_BYTES  16384
#define SRED_OFF  (SA_BYTES + 2 * SB_BYTES)
#define SMEM_TOTAL (SRED_OFF + 2048)

__global__ void assign_kernel(const float* __restrict__ F, int N, int K)
{
    extern __shared__ char smem[];
    uint32_t* sA = reinterpret_cast<uint32_t*>(smem);
    uint32_t* sB = reinterpret_cast<uint32_t*>(smem + SA_BYTES);
    float*    sBv = reinterpret_cast<float*>(smem + SRED_OFF);
    int*      sBi = reinterpret_cast<int*>(smem + SRED_OFF + 1024);

    const int tid  = threadIdx.x;
    const int wid  = tid >> 5;
    const int lane = tid & 31;
    const int mw = wid & 3;
    const int nw = wid >> 2;
    const int g  = lane >> 2;
    const int q  = lane & 3;
    const int p0 = blockIdx.x * 128;

    // ---- stage F tile into sA (convert + split once per block) ----
    {
        int row = tid >> 1;
        int prow = p0 + row; if (prow >= N) prow = N - 1;
        const int dbase = (tid & 1) * 64;
        const float4* src = reinterpret_cast<const float4*>(
            F + (size_t)prow * D_DIM + dbase);
        const int mwmt = row >> 4;
        const int rbit = (row >> 3) & 1;
        const int lrow4 = (row & 7) * 4;
        #pragma unroll
        for (int j = 0; j < 16; ++j) {
            float4 v = src[j];
            float vv[4] = { v.x, v.y, v.z, v.w };
            #pragma unroll
            for (int e = 0; e < 4; ++e) {
                int d = dbase + j * 4 + e;
                int ks = d >> 3;
                int r  = ((d >> 2) & 1) * 2 + rbit;
                int ln = lrow4 + (d & 3);
                uint32_t hb = f2tf32(vv[e]);
                uint32_t lb = f2tf32(vv[e] - __uint_as_float(hb));
                int base = (((mwmt * 16 + ks) * 2 + 0) * 32 + ln) * 4 + r;
                sA[base] = hb;
                sA[base + 128] = lb;   // split stride = 32*4 floats
            }
        }
    }

    float D[2][8][4];
    #pragma unroll
    for (int mt = 0; mt < 2; mt++)
        #pragma unroll
        for (int n = 0; n < 8; n++)
            #pragma unroll
            for (int e = 0; e < 4; e++) D[mt][n][e] = 0.0f;

    float bestv[4]; int besti[4]; float f2v[4];
    #pragma unroll
    for (int s = 0; s < 4; s++) {
        bestv[s] = __int_as_float(0x7f800000); besti[s] = 0;
        int row = p0 + mw * 32 + (s >> 1) * 16 + g + 8 * (s & 1);
        if (row >= N) row = N - 1;
        f2v[s] = g_f2[row];
    }

    // ---- B chunk loader helpers (thread t: center c=t>>1, 8 d's) ----
    const int lc   = tid >> 1;          // center 0..127
    const int ldh  = (tid & 1) * 8;     // d offset 0 or 8
    const int lnw  = lc >> 6;
    const int lnn  = (lc >> 3) & 7;
    const int lg4  = (lc & 7) * 4;
    const int bslotH = ((lnw * 8 + lnn) * 2 + 0) * 128;   // float base, split hi
    const int bslotL = ((lnw * 8 + lnn) * 2 + 1) * 128;

    const int nkt = K >> 7;
    const int it_total = nkt * 8;       // chunks of 16 d

    // prefetch + store chunk 0
    uint4 h0, h1, l0, l1;
    {
        size_t base = (size_t)lc * D_DIM + ldh;
        h0 = *reinterpret_cast<const uint4*>(g_Chi + base);
        h1 = *reinterpret_cast<const uint4*>(g_Chi + base + 4);
        l0 = *reinterpret_cast<const uint4*>(g_Clo + base);
        l1 = *reinterpret_cast<const uint4*>(g_Clo + base + 4);
    }
    {
        uint32_t* dst = sB;   // buffer 0
        uint32_t hv[8] = { h0.x,h0.y,h0.z,h0.w, h1.x,h1.y,h1.z,h1.w };
        uint32_t lv[8] = { l0.x,l0.y,l0.z,l0.w, l1.x,l1.y,l1.z,l1.w };
        #pragma unroll
        for (int j = 0; j < 8; ++j) {
            int dd = ldh + j;
            int off = (lg4 + (dd & 3)) * 4 + (dd >> 3) * 2 + ((dd >> 2) & 1);
            dst[bslotH + off] = hv[j];
            dst[bslotL + off] = lv[j];
        }
    }
    __syncthreads();

    for (int it = 0; it < it_total; ++it) {
        const int kt = it >> 3;
        const int dc = it & 7;
        const int cur = it & 1;
        const bool more = (it + 1 < it_total);

        if (more) {
            int nit = it + 1;
            size_t base = (size_t)(((nit >> 3) * 128) + lc) * D_DIM + (nit & 7) * 16 + ldh;
            h0 = *reinterpret_cast<const uint4*>(g_Chi + base);
            h1 = *reinterpret_cast<const uint4*>(g_Chi + base + 4);
            l0 = *reinterpret_cast<const uint4*>(g_Clo + base);
            l1 = *reinterpret_cast<const uint4*>(g_Clo + base + 4);
        }

        // ---- A fragments for this chunk: 8 x LDS.128 ----
        const int ks0 = dc * 2;
        uint4 ah[2][2], al[2][2];    // [mt][kk]
        #pragma unroll
        for (int mt = 0; mt < 2; ++mt)
            #pragma unroll
            for (int kk = 0; kk < 2; ++kk) {
                int b = ((((mw * 2 + mt) * 16 + (ks0 + kk)) * 2) * 32 + lane) * 4;
                ah[mt][kk] = *reinterpret_cast<const uint4*>(sA + b);
                al[mt][kk] = *reinterpret_cast<const uint4*>(sA + b + 128);
            }

        // ---- MMAs: loop n, 1 LDS.128 per (n,split), 12 MMAs per n ----
        const uint32_t* bbuf = sB + cur * (SB_BYTES / 4);
        #pragma unroll
        for (int n = 0; n < 8; ++n) {
            int fb = (((nw * 8 + n) * 2) * 32 + lane) * 4;
            uint4 bh = *reinterpret_cast<const uint4*>(bbuf + fb);
            uint4 bl = *reinterpret_cast<const uint4*>(bbuf + fb + 128);
            #pragma unroll
            for (int mt = 0; mt < 2; ++mt) {
                const uint32_t* AH0 = reinterpret_cast<const uint32_t*>(&ah[mt][0]);
                const uint32_t* AL0 = reinterpret_cast<const uint32_t*>(&al[mt][0]);
                const uint32_t* AH1 = reinterpret_cast<const uint32_t*>(&ah[mt][1]);
                const uint32_t* AL1 = reinterpret_cast<const uint32_t*>(&al[mt][1]);
                mma_tf32(D[mt][n], AH0, bh.x, bh.y);
                mma_tf32(D[mt][n], AL0, bh.x, bh.y);
                mma_tf32(D[mt][n], AH0, bl.x, bl.y);
                mma_tf32(D[mt][n], AH1, bh.z, bh.w);
                mma_tf32(D[mt][n], AL1, bh.z, bh.w);
                mma_tf32(D[mt][n], AH1, bl.z, bl.w);
            }
        }

        if (more) {
            uint32_t* dst = sB + (cur ^ 1) * (SB_BYTES / 4);
            uint32_t hv[8] = { h0.x,h0.y,h0.z,h0.w, h1.x,h1.y,h1.z,h1.w };
            uint32_t lv[8] = { l0.x,l0.y,l0.z,l0.w, l1.x,l1.y,l1.z,l1.w };
            #pragma unroll
            for (int j = 0; j < 8; ++j) {
                int dd = ldh + j;
                int off = (lg4 + (dd & 3)) * 4 + (dd >> 3) * 2 + ((dd >> 2) & 1);
                dst[bslotH + off] = hv[j];
                dst[bslotL + off] = lv[j];
            }
        }
        __syncthreads();

        // ---- k-tile boundary: score + argmin, reset D ----
        if (dc == 7) {
            #pragma unroll
            for (int n = 0; n < 8; ++n) {
                const int cb = kt * 128 + nw * 64 + n * 8 + 2 * q;
                const float c2a = g_c2[cb];
                const float c2b = g_c2[cb + 1];
                #pragma unroll
                for (int mt = 0; mt < 2; ++mt)
                    #pragma unroll
                    for (int h = 0; h < 2; ++h) {
                        const int s = mt * 2 + h;
                        float sa = (f2v[s] - 2.0f * D[mt][n][h * 2 + 0]) + c2a;
                        float sb = (f2v[s] - 2.0f * D[mt][n][h * 2 + 1]) + c2b;
                        if (sa < bestv[s]) { bestv[s] = sa; besti[s] = cb; }
                        if (sb < bestv[s]) { bestv[s] = sb; besti[s] = cb + 1; }
                        D[mt][n][h * 2 + 0] = 0.0f;
                        D[mt][n][h * 2 + 1] = 0.0f;
                    }
            }
        }
    }

    // ---- quad reduce + cross-nw reduce ----
    #pragma unroll
    for (int s = 0; s < 4; ++s) {
        float v  = bestv[s];
        int   ix = besti[s];
        #pragma unroll
        for (int off = 1; off < 4; off <<= 1) {
            float ov = __shfl_down_sync(0xffffffffu, v, off, 4);
            int   oi = __shfl_down_sync(0xffffffffu, ix, off, 4);
            if (ov < v || (ov == v && oi < ix)) { v = ov; ix = oi; }
        }
        if (q == 0) {
            int row = mw * 32 + (s >> 1) * 16 + g + 8 * (s & 1);
            sBv[nw * 128 + row] = v;
            sBi[nw * 128 + row] = ix;
        }
    }
    __syncthreads();

    if (tid < 128) {
        float v0 = sBv[tid];       int i0 = sBi[tid];
        float v1 = sBv[128 + tid]; int i1 = sBi[128 + tid];
        int best = (v1 < v0 || (v1 == v0 && i1 < i0)) ? i1 : i0;
        if (p0 + tid < N) g_assign[p0 + tid] = best;
    }
}

// ---------------------------------------------------------------------------
__global__ void seg_kernel(const float* __restrict__ F, int N) {
    int w = (blockIdx.x * blockDim.x + threadIdx.x) >> 5;
    int lane = threadIdx.x & 31;
    if (w >= N) return;
    int a = g_assign[w];
    float4 v = reinterpret_cast<const float4*>(F + (size_t)w * D_DIM)[lane];
    float* dst = g_sums + (size_t)a * D_DIM + lane * 4;
    asm volatile("red.global.add.v4.f32 [%0], {%1, %2, %3, %4};"
                 :: "l"(dst), "f"(v.x), "f"(v.y), "f"(v.z), "f"(v.w)
                 : "memory");
    if (lane == 0) atomicAdd(&g_counts[a], 1);
}

__global__ void final_kernel(float* __restrict__ out, int KD, int nAssign) {
    int i = blockIdx.x * blockDim.x + threadIdx.x;
    if (i < KD) {
        float c = (float)g_counts[i / D_DIM];
        out[i] = g_sums[i] / fmaxf(c, 1.0f);
    } else {
        int a = i - KD;
        if (a < nAssign) out[KD + a] = (float)g_assign[a];
    }
}

// ---------------------------------------------------------------------------
extern "C" void kernel_launch(void* const* d_in, const int* in_sizes, int n_in,
                              void* d_out, int out_size)
{
    (void)n_in;
    const float* F = (const float*)d_in[0];
    const float* C = (const float*)d_in[1];
    const int D = D_DIM;
    const int N = in_sizes[0] / D;
    const int K = in_sizes[1] / D;
    float* out = (float*)d_out;
    const int KD = K * D;

    cudaFuncSetAttribute(assign_kernel,
                         cudaFuncAttributeMaxDynamicSharedMemorySize, SMEM_TOTAL);

    const int prepThreads = (N + K) * 32;
    prep_kernel<<<(prepThreads + 255) / 256, 256>>>(F, C, N, K);
    assign_kernel<<<(N + 127) / 128, 256, SMEM_TOTAL>>>(F, N, K);
    seg_kernel<<<(N + 7) / 8, 256>>>(F, N);

    int centersPart, assignPart;
    if (out_size >= KD + N)      { centersPart = KD; assignPart = N; }
    else if (out_size >= KD)     { centersPart = KD; assignPart = out_size - KD; }
    else                         { centersPart = 0;  assignPart = out_size; }
    int total = centersPart + assignPart;
    if (total > 0)
        final_kernel<<<(total + 255) / 256, 256>>>(out, centersPart, assignPart);
}